// round 11
// baseline (speedup 1.0000x reference)
#include <cuda_runtime.h>
#include <cuda_bf16.h>

#define NN 20000
#define NP2 20096            // 157 * 128, row pad for gemm2
#define NE 320000
#define F0 10
#define F1 256
#define F2 128

// ---------------- scratch (device globals; zero-initialized) ----------------
__device__ int   g_cnt[NN];            // re-zeroed by k_scan_fused each run
__device__ int   g_rowptr[NN + 1];
__device__ int   g_rank[NE];           // per-edge rank within its dst bucket
__device__ int   g_csr[NE];            // src index per CSR slot (grouped by dst)
__device__ float g_dinv[NN];
__device__ __nv_bfloat16 g_h1hi[NP2 * F1];   // relu(A@x@W1+b1) split-bf16 hi
__device__ __nv_bfloat16 g_h1lo[NP2 * F1];   // lo
__device__ __nv_bfloat16 g_w2thi[F2 * F1];   // W2^T [n][k] split-bf16 hi
__device__ __nv_bfloat16 g_w2tlo[F2 * F1];   // lo
__device__ float g_t2[NP2 * F2];       // h1 @ W2
__device__ float g_t3[NN];             // relu(A@t2+b2) @ W3

// ------- hist (edge degree + rank) and, in spare blocks, W2 split-bf16^T ----
#define HIST_BLKS ((NE + 255) / 256)         // 1250
__global__ void k_hist(const int* __restrict__ dst, const float* __restrict__ W2) {
    if (blockIdx.x < HIST_BLKS) {
        int e = blockIdx.x * blockDim.x + threadIdx.x;
        if (e < NE) g_rank[e] = atomicAdd(&g_cnt[dst[e]], 1);
    } else {
        int i = (blockIdx.x - HIST_BLKS) * blockDim.x + threadIdx.x;
        if (i < F1 * F2) {
            int k = i / F2, n = i % F2;
            float v = W2[i];
            __nv_bfloat16 h = __float2bfloat16(v);
            __nv_bfloat16 l = __float2bfloat16(v - __bfloat162float(h));
            g_w2thi[n * F1 + k] = h;
            g_w2tlo[n * F1 + k] = l;
        }
    }
}

// Single-block scan, one sync round; fuses g_dinv and re-zeroes g_cnt.
__global__ void k_scan_fused() {
    __shared__ int wsum[32];
    const int PER = 20;                       // 1024*20 = 20480 >= NN
    int tid  = threadIdx.x;
    int lane = tid & 31, w = tid >> 5;
    int base = tid * PER;

    int pref[PER];
    int s = 0;
    #pragma unroll
    for (int j = 0; j < PER; j++) {
        int idx = base + j;
        int c = 0;
        if (idx < NN) {
            c = g_cnt[idx];
            g_cnt[idx] = 0;                   // self-zero for next replay
            g_dinv[idx] = rsqrtf((float)(c + 1));
        }
        pref[j] = s;
        s += c;
    }

    int incl = s;
    #pragma unroll
    for (int o = 1; o < 32; o <<= 1) {
        int t = __shfl_up_sync(0xffffffffu, incl, o);
        if (lane >= o) incl += t;
    }
    if (lane == 31) wsum[w] = incl;
    __syncthreads();
    if (w == 0) {
        int t = wsum[lane];
        int ss = t;
        #pragma unroll
        for (int o = 1; o < 32; o <<= 1) {
            int u = __shfl_up_sync(0xffffffffu, ss, o);
            if (lane >= o) ss += u;
        }
        wsum[lane] = ss - t;
    }
    __syncthreads();

    int thread_excl = wsum[w] + incl - s;
    #pragma unroll
    for (int j = 0; j < PER; j++) {
        int idx = base + j;
        if (idx < NN) g_rowptr[idx] = thread_excl + pref[j];
    }
    if (tid == 1023) g_rowptr[NN] = thread_excl + s;  // == NE
}

// Atomic-free scatter: pos = rowptr[dst] + rank (rank captured during hist).
__global__ void k_scatter(const int* __restrict__ src, const int* __restrict__ dst) {
    int e = blockIdx.x * blockDim.x + threadIdx.x;
    if (e < NE) {
        int pos = g_rowptr[dst[e]] + g_rank[e];
        g_csr[pos] = src[e];
    }
}

// -------- layer 1 fused: aggregate x (F=10) + @W1 + b1 + relu + split ------
// 512 threads = 16 warps = 16 nodes per block. W1 (10x256) + b1 staged in smem.
// Per warp: gather the 10-wide normalized aggregate (lanes 0-9), then each
// lane produces 8 h1 columns via shuffle-broadcast FMAs; emit split-bf16.
__global__ void __launch_bounds__(512) k_layer1(const float* __restrict__ x,
                                                const float* __restrict__ W1,
                                                const float* __restrict__ b1) {
    __shared__ float Ws[F0 * F1];
    __shared__ float bs[F1];
    int t = threadIdx.x;
    for (int i = t; i < F0 * F1; i += 512) Ws[i] = W1[i];
    if (t < F1) bs[t] = b1[t];
    __syncthreads();

    int w = blockIdx.x * 16 + (t >> 5);
    int lane = t & 31;
    if (w >= NN) return;

    float dn = g_dinv[w];
    float acc = 0.f;
    if (lane < F0) acc = dn * x[w * F0 + lane];
    int b = g_rowptr[w], e = g_rowptr[w + 1];
    for (int i = b; i < e; i++) {
        int s = g_csr[i];
        float c = g_dinv[s];
        if (lane < F0) acc += c * x[s * F0 + lane];
    }
    acc *= dn;                                // aggx value for this lane's feature

    // broadcast the 10 aggregate features to all lanes
    float a[F0];
    #pragma unroll
    for (int k = 0; k < F0; k++) a[k] = __shfl_sync(0xffffffffu, acc, k);

    #pragma unroll
    for (int j = 0; j < 8; j++) {
        int col = lane + j * 32;
        float o = bs[col];
        #pragma unroll
        for (int k = 0; k < F0; k++) o += a[k] * Ws[k * F1 + col];
        float v = fmaxf(o, 0.f);
        __nv_bfloat16 h = __float2bfloat16(v);
        __nv_bfloat16 l = __float2bfloat16(v - __bfloat162float(h));
        g_h1hi[w * F1 + col] = h;
        g_h1lo[w * F1 + col] = l;
    }
}

// ---------------- layer 2 GEMM (tensor cores, split-bf16) -------------------
// D[NP2,128] = h1[NP2,256] @ W2[256,128], 3-pass split bf16:
//   acc += a_hi*b_hi + a_lo*b_hi + a_hi*b_lo     (lo*lo dropped, ~2^-16)
__device__ __forceinline__ void mma_bf16(float* d, const unsigned* a,
                                         unsigned b0, unsigned b1) {
    asm volatile(
        "mma.sync.aligned.m16n8k16.row.col.f32.bf16.bf16.f32 "
        "{%0,%1,%2,%3}, {%4,%5,%6,%7}, {%8,%9}, {%0,%1,%2,%3};\n"
        : "+f"(d[0]), "+f"(d[1]), "+f"(d[2]), "+f"(d[3])
        : "r"(a[0]), "r"(a[1]), "r"(a[2]), "r"(a[3]), "r"(b0), "r"(b1));
}

#define KP 72   // smem B row stride (elems): conflict-free, 16B-aligned

__global__ void __launch_bounds__(256, 2) k_gemm2() {
    __shared__ __nv_bfloat16 bhi[F2 * KP];   // [n][k-chunk]
    __shared__ __nv_bfloat16 blo[F2 * KP];
    int t = threadIdx.x;
    int w = t >> 5, lane = t & 31;
    int r0 = blockIdx.x * 128;
    int mrow = r0 + w * 16 + (lane >> 2);    // A/D fragment top row
    int kq = (lane & 3) * 2;                 // k offset within 8

    float acc[16][4];
    #pragma unroll
    for (int i = 0; i < 16; i++)
        #pragma unroll
        for (int j = 0; j < 4; j++) acc[i][j] = 0.f;

    for (int kc = 0; kc < F1; kc += 64) {
        #pragma unroll
        for (int i = 0; i < 4; i++) {
            int idx = t + i * 256;           // 0..1023
            int n = idx >> 3, seg = idx & 7; // 8 x uint4 per row
            *(uint4*)&bhi[n * KP + seg * 8] =
                *(const uint4*)&g_w2thi[n * F1 + kc + seg * 8];
            *(uint4*)&blo[n * KP + seg * 8] =
                *(const uint4*)&g_w2tlo[n * F1 + kc + seg * 8];
        }
        __syncthreads();

        #pragma unroll
        for (int ks = 0; ks < 4; ks++) {
            int kg = kc + ks * 16 + kq;      // global k for A
            unsigned ahi[4], alo[4];
            ahi[0] = *(const unsigned*)&g_h1hi[ mrow      * F1 + kg];
            ahi[1] = *(const unsigned*)&g_h1hi[(mrow + 8) * F1 + kg];
            ahi[2] = *(const unsigned*)&g_h1hi[ mrow      * F1 + kg + 8];
            ahi[3] = *(const unsigned*)&g_h1hi[(mrow + 8) * F1 + kg + 8];
            alo[0] = *(const unsigned*)&g_h1lo[ mrow      * F1 + kg];
            alo[1] = *(const unsigned*)&g_h1lo[(mrow + 8) * F1 + kg];
            alo[2] = *(const unsigned*)&g_h1lo[ mrow      * F1 + kg + 8];
            alo[3] = *(const unsigned*)&g_h1lo[(mrow + 8) * F1 + kg + 8];
            int kl = ks * 16 + kq;           // chunk-local k for B
            #pragma unroll
            for (int nt = 0; nt < 16; nt++) {
                int nrow = nt * 8 + (lane >> 2);
                unsigned bh0 = *(const unsigned*)&bhi[nrow * KP + kl];
                unsigned bh1 = *(const unsigned*)&bhi[nrow * KP + kl + 8];
                unsigned bl0 = *(const unsigned*)&blo[nrow * KP + kl];
                unsigned bl1 = *(const unsigned*)&blo[nrow * KP + kl + 8];
                mma_bf16(acc[nt], ahi, bh0, bh1);
                mma_bf16(acc[nt], alo, bh0, bh1);
                mma_bf16(acc[nt], ahi, bl0, bl1);
            }
        }
        __syncthreads();
    }

    #pragma unroll
    for (int nt = 0; nt < 16; nt++) {
        int col = nt * 8 + (lane & 3) * 2;
        *(float2*)&g_t2[ mrow      * F2 + col] = make_float2(acc[nt][0], acc[nt][1]);
        *(float2*)&g_t2[(mrow + 8) * F2 + col] = make_float2(acc[nt][2], acc[nt][3]);
    }
}

// ------- layer 2 aggregation + bias + relu + layer-3 dot (fused) -----------
__global__ void k_agg2dot(const float* __restrict__ b2, const float* __restrict__ W3) {
    int w = (blockIdx.x * blockDim.x + threadIdx.x) >> 5;
    int lane = threadIdx.x & 31;
    if (w >= NN) return;
    float dn = g_dinv[w];
    int c4 = lane * 4;
    float4 sv = *(const float4*)&g_t2[w * F2 + c4];
    float4 acc = make_float4(dn * sv.x, dn * sv.y, dn * sv.z, dn * sv.w);
    int b = g_rowptr[w], e = g_rowptr[w + 1];
    for (int i = b; i < e; i++) {
        int s = g_csr[i];
        float c = g_dinv[s];
        float4 v = *(const float4*)&g_t2[s * F2 + c4];
        acc.x += c * v.x; acc.y += c * v.y; acc.z += c * v.z; acc.w += c * v.w;
    }
    float4 bb = *(const float4*)&b2[c4];
    float4 h;
    h.x = fmaxf(dn * acc.x + bb.x, 0.f);
    h.y = fmaxf(dn * acc.y + bb.y, 0.f);
    h.z = fmaxf(dn * acc.z + bb.z, 0.f);
    h.w = fmaxf(dn * acc.w + bb.w, 0.f);
    float4 v3 = *(const float4*)&W3[c4];
    float s = h.x * v3.x + h.y * v3.y + h.z * v3.z + h.w * v3.w;
    #pragma unroll
    for (int o = 16; o > 0; o >>= 1) s += __shfl_down_sync(0xffffffffu, s, o);
    if (lane == 0) g_t3[w] = s;
}

// ---------------- final aggregation over t3 --------------------------------
__global__ void k_agg3(const float* __restrict__ b3, float* __restrict__ out) {
    int n = blockIdx.x * blockDim.x + threadIdx.x;
    if (n >= NN) return;
    float dn = g_dinv[n];
    float acc = dn * g_t3[n];
    int b = g_rowptr[n], e = g_rowptr[n + 1];
    for (int i = b; i < e; i++) {
        int s = g_csr[i];
        acc += g_dinv[s] * g_t3[s];
    }
    out[n] = dn * acc + b3[0];
}

// ---------------- launch ----------------------------------------------------
extern "C" void kernel_launch(void* const* d_in, const int* in_sizes, int n_in,
                              void* d_out, int out_size) {
    const float* x   = (const float*)d_in[0];
    const int*   ei  = (const int*)d_in[1];
    const float* W1  = (const float*)d_in[2];
    const float* b1  = (const float*)d_in[3];
    const float* W2  = (const float*)d_in[4];
    const float* b2  = (const float*)d_in[5];
    const float* W3  = (const float*)d_in[6];
    const float* b3  = (const float*)d_in[7];
    float* out = (float*)d_out;
    const int* src = ei;
    const int* dst = ei + NE;

    k_hist<<<HIST_BLKS + 128, 256>>>(dst, W2);     // hist + W2 split-bf16^T
    k_scan_fused<<<1, 1024>>>();                   // scan + dinv + cnt re-zero
    k_scatter<<<(NE + 255) / 256, 256>>>(src, dst);

    k_layer1<<<(NN + 15) / 16, 512>>>(x, W1, b1);  // aggx + gemm1 fused
    k_gemm2<<<NP2 / 128, 256>>>();
    k_agg2dot<<<(NN * 32 + 255) / 256, 256>>>(b2, W3);
    k_agg3<<<(NN + 255) / 256, 256>>>(b3, out);
}

// round 13
// speedup vs baseline: 1.0274x; 1.0274x over previous
#include <cuda_runtime.h>
#include <cuda_bf16.h>

#define NN 20000
#define NP2 20096            // 157 * 128, row pad for gemm2
#define NE 320000
#define F0 10
#define F1 256
#define F2 128

// ---------------- scratch (device globals; zero-initialized) ----------------
__device__ int   g_cnt[NN];            // re-zeroed by k_scan_fused each run
__device__ int   g_rowptr[NN + 1];
__device__ int   g_rank[NE];           // per-edge rank within its dst bucket
__device__ int   g_csr[NE];            // src index per CSR slot (grouped by dst)
__device__ float g_dinv[NN];
__device__ __nv_bfloat16 g_h1hi[NP2 * F1];   // relu(A@x@W1+b1) split-bf16 hi
__device__ __nv_bfloat16 g_h1lo[NP2 * F1];   // lo
__device__ __nv_bfloat16 g_w2thi[F2 * F1];   // W2^T [n][k] split-bf16 hi
__device__ __nv_bfloat16 g_w2tlo[F2 * F1];   // lo
__device__ float g_t2[NP2 * F2];       // h1 @ W2
__device__ float g_t3[NN];             // relu(A@t2+b2) @ W3

// ------- hist (edge degree + rank) and, in spare blocks, W2 split-bf16^T ----
#define HIST_BLKS ((NE + 255) / 256)         // 1250
__global__ void k_hist(const int* __restrict__ dst, const float* __restrict__ W2) {
    if (blockIdx.x < HIST_BLKS) {
        int e = blockIdx.x * blockDim.x + threadIdx.x;
        if (e < NE) g_rank[e] = atomicAdd(&g_cnt[dst[e]], 1);
    } else {
        int i = (blockIdx.x - HIST_BLKS) * blockDim.x + threadIdx.x;
        if (i < F1 * F2) {
            int k = i / F2, n = i % F2;
            float v = W2[i];
            __nv_bfloat16 h = __float2bfloat16(v);
            __nv_bfloat16 l = __float2bfloat16(v - __bfloat162float(h));
            g_w2thi[n * F1 + k] = h;
            g_w2tlo[n * F1 + k] = l;
        }
    }
}

// Single-block scan, one sync round; fuses g_dinv and re-zeroes g_cnt.
__global__ void k_scan_fused() {
    __shared__ int wsum[32];
    const int PER = 20;                       // 1024*20 = 20480 >= NN
    int tid  = threadIdx.x;
    int lane = tid & 31, w = tid >> 5;
    int base = tid * PER;

    int pref[PER];
    int s = 0;
    #pragma unroll
    for (int j = 0; j < PER; j++) {
        int idx = base + j;
        int c = 0;
        if (idx < NN) {
            c = g_cnt[idx];
            g_cnt[idx] = 0;                   // self-zero for next replay
            g_dinv[idx] = rsqrtf((float)(c + 1));
        }
        pref[j] = s;
        s += c;
    }

    int incl = s;
    #pragma unroll
    for (int o = 1; o < 32; o <<= 1) {
        int t = __shfl_up_sync(0xffffffffu, incl, o);
        if (lane >= o) incl += t;
    }
    if (lane == 31) wsum[w] = incl;
    __syncthreads();
    if (w == 0) {
        int t = wsum[lane];
        int ss = t;
        #pragma unroll
        for (int o = 1; o < 32; o <<= 1) {
            int u = __shfl_up_sync(0xffffffffu, ss, o);
            if (lane >= o) ss += u;
        }
        wsum[lane] = ss - t;
    }
    __syncthreads();

    int thread_excl = wsum[w] + incl - s;
    #pragma unroll
    for (int j = 0; j < PER; j++) {
        int idx = base + j;
        if (idx < NN) g_rowptr[idx] = thread_excl + pref[j];
    }
    if (tid == 1023) g_rowptr[NN] = thread_excl + s;  // == NE
}

// Atomic-free scatter: pos = rowptr[dst] + rank (rank captured during hist).
__global__ void k_scatter(const int* __restrict__ src, const int* __restrict__ dst) {
    int e = blockIdx.x * blockDim.x + threadIdx.x;
    if (e < NE) {
        int pos = g_rowptr[dst[e]] + g_rank[e];
        g_csr[pos] = src[e];
    }
}

// -------- layer 1 fused: aggregate x (F=10) + @W1 + b1 + relu + split ------
// 4-way unrolled gather: 4 independent csr->dinv->x chains in flight (MLP 4).
__global__ void __launch_bounds__(512) k_layer1(const float* __restrict__ x,
                                                const float* __restrict__ W1,
                                                const float* __restrict__ b1) {
    __shared__ float Ws[F0 * F1];
    __shared__ float bs[F1];
    int t = threadIdx.x;
    for (int i = t; i < F0 * F1; i += 512) Ws[i] = W1[i];
    if (t < F1) bs[t] = b1[t];
    __syncthreads();

    int w = blockIdx.x * 16 + (t >> 5);
    int lane = t & 31;
    if (w >= NN) return;

    float dn = g_dinv[w];
    float acc = 0.f;
    if (lane < F0) acc = dn * x[w * F0 + lane];
    int b = g_rowptr[w], e = g_rowptr[w + 1];
    int i = b;
    for (; i + 4 <= e; i += 4) {
        int s0 = g_csr[i + 0];
        int s1 = g_csr[i + 1];
        int s2 = g_csr[i + 2];
        int s3 = g_csr[i + 3];
        float c0 = g_dinv[s0];
        float c1 = g_dinv[s1];
        float c2 = g_dinv[s2];
        float c3 = g_dinv[s3];
        if (lane < F0) {
            float x0 = x[s0 * F0 + lane];
            float x1 = x[s1 * F0 + lane];
            float x2 = x[s2 * F0 + lane];
            float x3 = x[s3 * F0 + lane];
            acc += c0 * x0;
            acc += c1 * x1;
            acc += c2 * x2;
            acc += c3 * x3;
        }
    }
    for (; i < e; i++) {
        int s = g_csr[i];
        float c = g_dinv[s];
        if (lane < F0) acc += c * x[s * F0 + lane];
    }
    acc *= dn;                                // aggx value for this lane's feature

    // broadcast the 10 aggregate features to all lanes
    float a[F0];
    #pragma unroll
    for (int k = 0; k < F0; k++) a[k] = __shfl_sync(0xffffffffu, acc, k);

    #pragma unroll
    for (int j = 0; j < 8; j++) {
        int col = lane + j * 32;
        float o = bs[col];
        #pragma unroll
        for (int k = 0; k < F0; k++) o += a[k] * Ws[k * F1 + col];
        float v = fmaxf(o, 0.f);
        __nv_bfloat16 h = __float2bfloat16(v);
        __nv_bfloat16 l = __float2bfloat16(v - __bfloat162float(h));
        g_h1hi[w * F1 + col] = h;
        g_h1lo[w * F1 + col] = l;
    }
}

// ---------------- layer 2 GEMM (tensor cores, split-bf16) -------------------
// D[NP2,128] = h1[NP2,256] @ W2[256,128], 3-pass split bf16:
//   acc += a_hi*b_hi + a_lo*b_hi + a_hi*b_lo     (lo*lo dropped, ~2^-16)
__device__ __forceinline__ void mma_bf16(float* d, const unsigned* a,
                                         unsigned b0, unsigned b1) {
    asm volatile(
        "mma.sync.aligned.m16n8k16.row.col.f32.bf16.bf16.f32 "
        "{%0,%1,%2,%3}, {%4,%5,%6,%7}, {%8,%9}, {%0,%1,%2,%3};\n"
        : "+f"(d[0]), "+f"(d[1]), "+f"(d[2]), "+f"(d[3])
        : "r"(a[0]), "r"(a[1]), "r"(a[2]), "r"(a[3]), "r"(b0), "r"(b1));
}

#define KP 72   // smem B row stride (elems): conflict-free, 16B-aligned

__global__ void __launch_bounds__(256, 2) k_gemm2() {
    __shared__ __nv_bfloat16 bhi[F2 * KP];   // [n][k-chunk]
    __shared__ __nv_bfloat16 blo[F2 * KP];
    int t = threadIdx.x;
    int w = t >> 5, lane = t & 31;
    int r0 = blockIdx.x * 128;
    int mrow = r0 + w * 16 + (lane >> 2);    // A/D fragment top row
    int kq = (lane & 3) * 2;                 // k offset within 8

    float acc[16][4];
    #pragma unroll
    for (int i = 0; i < 16; i++)
        #pragma unroll
        for (int j = 0; j < 4; j++) acc[i][j] = 0.f;

    for (int kc = 0; kc < F1; kc += 64) {
        #pragma unroll
        for (int i = 0; i < 4; i++) {
            int idx = t + i * 256;           // 0..1023
            int n = idx >> 3, seg = idx & 7; // 8 x uint4 per row
            *(uint4*)&bhi[n * KP + seg * 8] =
                *(const uint4*)&g_w2thi[n * F1 + kc + seg * 8];
            *(uint4*)&blo[n * KP + seg * 8] =
                *(const uint4*)&g_w2tlo[n * F1 + kc + seg * 8];
        }
        __syncthreads();

        #pragma unroll
        for (int ks = 0; ks < 4; ks++) {
            int kg = kc + ks * 16 + kq;      // global k for A
            unsigned ahi[4], alo[4];
            ahi[0] = *(const unsigned*)&g_h1hi[ mrow      * F1 + kg];
            ahi[1] = *(const unsigned*)&g_h1hi[(mrow + 8) * F1 + kg];
            ahi[2] = *(const unsigned*)&g_h1hi[ mrow      * F1 + kg + 8];
            ahi[3] = *(const unsigned*)&g_h1hi[(mrow + 8) * F1 + kg + 8];
            alo[0] = *(const unsigned*)&g_h1lo[ mrow      * F1 + kg];
            alo[1] = *(const unsigned*)&g_h1lo[(mrow + 8) * F1 + kg];
            alo[2] = *(const unsigned*)&g_h1lo[ mrow      * F1 + kg + 8];
            alo[3] = *(const unsigned*)&g_h1lo[(mrow + 8) * F1 + kg + 8];
            int kl = ks * 16 + kq;           // chunk-local k for B
            #pragma unroll
            for (int nt = 0; nt < 16; nt++) {
                int nrow = nt * 8 + (lane >> 2);
                unsigned bh0 = *(const unsigned*)&bhi[nrow * KP + kl];
                unsigned bh1 = *(const unsigned*)&bhi[nrow * KP + kl + 8];
                unsigned bl0 = *(const unsigned*)&blo[nrow * KP + kl];
                unsigned bl1 = *(const unsigned*)&blo[nrow * KP + kl + 8];
                mma_bf16(acc[nt], ahi, bh0, bh1);
                mma_bf16(acc[nt], alo, bh0, bh1);
                mma_bf16(acc[nt], ahi, bl0, bl1);
            }
        }
        __syncthreads();
    }

    #pragma unroll
    for (int nt = 0; nt < 16; nt++) {
        int col = nt * 8 + (lane & 3) * 2;
        *(float2*)&g_t2[ mrow      * F2 + col] = make_float2(acc[nt][0], acc[nt][1]);
        *(float2*)&g_t2[(mrow + 8) * F2 + col] = make_float2(acc[nt][2], acc[nt][3]);
    }
}

// ------- layer 2 aggregation + bias + relu + layer-3 dot (fused) -----------
// 4-way unrolled gather: 4 independent csr->dinv->t2 chains in flight.
__global__ void k_agg2dot(const float* __restrict__ b2, const float* __restrict__ W3) {
    int w = (blockIdx.x * blockDim.x + threadIdx.x) >> 5;
    int lane = threadIdx.x & 31;
    if (w >= NN) return;
    float dn = g_dinv[w];
    int c4 = lane * 4;
    float4 sv = *(const float4*)&g_t2[w * F2 + c4];
    float4 acc = make_float4(dn * sv.x, dn * sv.y, dn * sv.z, dn * sv.w);
    int b = g_rowptr[w], e = g_rowptr[w + 1];
    int i = b;
    for (; i + 4 <= e; i += 4) {
        int s0 = g_csr[i + 0];
        int s1 = g_csr[i + 1];
        int s2 = g_csr[i + 2];
        int s3 = g_csr[i + 3];
        float c0 = g_dinv[s0];
        float c1 = g_dinv[s1];
        float c2 = g_dinv[s2];
        float c3 = g_dinv[s3];
        float4 v0 = *(const float4*)&g_t2[s0 * F2 + c4];
        float4 v1 = *(const float4*)&g_t2[s1 * F2 + c4];
        float4 v2 = *(const float4*)&g_t2[s2 * F2 + c4];
        float4 v3v = *(const float4*)&g_t2[s3 * F2 + c4];
        acc.x += c0 * v0.x; acc.y += c0 * v0.y; acc.z += c0 * v0.z; acc.w += c0 * v0.w;
        acc.x += c1 * v1.x; acc.y += c1 * v1.y; acc.z += c1 * v1.z; acc.w += c1 * v1.w;
        acc.x += c2 * v2.x; acc.y += c2 * v2.y; acc.z += c2 * v2.z; acc.w += c2 * v2.w;
        acc.x += c3 * v3v.x; acc.y += c3 * v3v.y; acc.z += c3 * v3v.z; acc.w += c3 * v3v.w;
    }
    for (; i < e; i++) {
        int s = g_csr[i];
        float c = g_dinv[s];
        float4 v = *(const float4*)&g_t2[s * F2 + c4];
        acc.x += c * v.x; acc.y += c * v.y; acc.z += c * v.z; acc.w += c * v.w;
    }
    float4 bb = *(const float4*)&b2[c4];
    float4 h;
    h.x = fmaxf(dn * acc.x + bb.x, 0.f);
    h.y = fmaxf(dn * acc.y + bb.y, 0.f);
    h.z = fmaxf(dn * acc.z + bb.z, 0.f);
    h.w = fmaxf(dn * acc.w + bb.w, 0.f);
    float4 v3 = *(const float4*)&W3[c4];
    float s = h.x * v3.x + h.y * v3.y + h.z * v3.z + h.w * v3.w;
    #pragma unroll
    for (int o = 16; o > 0; o >>= 1) s += __shfl_down_sync(0xffffffffu, s, o);
    if (lane == 0) g_t3[w] = s;
}

// ---------------- final aggregation over t3 (4-way unrolled) ----------------
__global__ void k_agg3(const float* __restrict__ b3, float* __restrict__ out) {
    int n = blockIdx.x * blockDim.x + threadIdx.x;
    if (n >= NN) return;
    float dn = g_dinv[n];
    float acc = dn * g_t3[n];
    int b = g_rowptr[n], e = g_rowptr[n + 1];
    int i = b;
    for (; i + 4 <= e; i += 4) {
        int s0 = g_csr[i + 0];
        int s1 = g_csr[i + 1];
        int s2 = g_csr[i + 2];
        int s3 = g_csr[i + 3];
        acc += g_dinv[s0] * g_t3[s0];
        acc += g_dinv[s1] * g_t3[s1];
        acc += g_dinv[s2] * g_t3[s2];
        acc += g_dinv[s3] * g_t3[s3];
    }
    for (; i < e; i++) {
        int s = g_csr[i];
        acc += g_dinv[s] * g_t3[s];
    }
    out[n] = dn * acc + b3[0];
}

// ---------------- launch ----------------------------------------------------
extern "C" void kernel_launch(void* const* d_in, const int* in_sizes, int n_in,
                              void* d_out, int out_size) {
    const float* x   = (const float*)d_in[0];
    const int*   ei  = (const int*)d_in[1];
    const float* W1  = (const float*)d_in[2];
    const float* b1  = (const float*)d_in[3];
    const float* W2  = (const float*)d_in[4];
    const float* b2  = (const float*)d_in[5];
    const float* W3  = (const float*)d_in[6];
    const float* b3  = (const float*)d_in[7];
    float* out = (float*)d_out;
    const int* src = ei;
    const int* dst = ei + NE;

    k_hist<<<HIST_BLKS + 128, 256>>>(dst, W2);     // hist + W2 split-bf16^T
    k_scan_fused<<<1, 1024>>>();                   // scan + dinv + cnt re-zero
    k_scatter<<<(NE + 255) / 256, 256>>>(src, dst);

    k_layer1<<<(NN + 15) / 16, 512>>>(x, W1, b1);  // aggx + gemm1 fused
    k_gemm2<<<NP2 / 128, 256>>>();
    k_agg2dot<<<(NN * 32 + 255) / 256, 256>>>(b2, W3);
    k_agg3<<<(NN + 255) / 256, 256>>>(b3, out);
}

// round 15
// speedup vs baseline: 1.0282x; 1.0008x over previous
#include <cuda_runtime.h>
#include <cuda_bf16.h>

#define NN 20000
#define NP2 20096            // 157 * 128, row pad for gemm2
#define NE 320000
#define F0 10
#define F1 256
#define F2 128

// ---------------- scratch (device globals; zero-initialized) ----------------
__device__ int   g_cnt[NN];            // re-zeroed by k_scan_fused each run
__device__ int   g_rowptr[NN + 1];
__device__ int   g_rank[NE];           // per-edge rank within its dst bucket
__device__ int   g_csr[NE];            // src index per CSR slot (grouped by dst)
__device__ float g_dinv[NN];
__device__ __nv_bfloat16 g_h1hi[NP2 * F1];   // relu(A@x@W1+b1) split-bf16 hi
__device__ __nv_bfloat16 g_h1lo[NP2 * F1];   // lo
__device__ __nv_bfloat16 g_w2thi[F2 * F1];   // W2^T [n][k] split-bf16 hi
__device__ __nv_bfloat16 g_w2tlo[F2 * F1];   // lo
__device__ float g_t2[NP2 * F2];       // h1 @ W2
__device__ float g_t3[NN];             // relu(A@t2+b2) @ W3

// ------- hist (edge degree + rank) and, in spare blocks, W2 split-bf16^T ----
#define HIST_BLKS ((NE + 255) / 256)         // 1250
__global__ void k_hist(const int* __restrict__ dst, const float* __restrict__ W2) {
    if (blockIdx.x < HIST_BLKS) {
        int e = blockIdx.x * blockDim.x + threadIdx.x;
        if (e < NE) g_rank[e] = atomicAdd(&g_cnt[dst[e]], 1);
    } else {
        int i = (blockIdx.x - HIST_BLKS) * blockDim.x + threadIdx.x;
        if (i < F1 * F2) {
            int k = i / F2, n = i % F2;
            float v = W2[i];
            __nv_bfloat16 h = __float2bfloat16(v);
            __nv_bfloat16 l = __float2bfloat16(v - __bfloat162float(h));
            g_w2thi[n * F1 + k] = h;
            g_w2tlo[n * F1 + k] = l;
        }
    }
}

// Single-block scan, one sync round; fuses g_dinv and re-zeroes g_cnt.
__global__ void k_scan_fused() {
    __shared__ int wsum[32];
    const int PER = 20;                       // 1024*20 = 20480 >= NN
    int tid  = threadIdx.x;
    int lane = tid & 31, w = tid >> 5;
    int base = tid * PER;

    int pref[PER];
    int s = 0;
    #pragma unroll
    for (int j = 0; j < PER; j++) {
        int idx = base + j;
        int c = 0;
        if (idx < NN) {
            c = g_cnt[idx];
            g_cnt[idx] = 0;                   // self-zero for next replay
            g_dinv[idx] = rsqrtf((float)(c + 1));
        }
        pref[j] = s;
        s += c;
    }

    int incl = s;
    #pragma unroll
    for (int o = 1; o < 32; o <<= 1) {
        int t = __shfl_up_sync(0xffffffffu, incl, o);
        if (lane >= o) incl += t;
    }
    if (lane == 31) wsum[w] = incl;
    __syncthreads();
    if (w == 0) {
        int t = wsum[lane];
        int ss = t;
        #pragma unroll
        for (int o = 1; o < 32; o <<= 1) {
            int u = __shfl_up_sync(0xffffffffu, ss, o);
            if (lane >= o) ss += u;
        }
        wsum[lane] = ss - t;
    }
    __syncthreads();

    int thread_excl = wsum[w] + incl - s;
    #pragma unroll
    for (int j = 0; j < PER; j++) {
        int idx = base + j;
        if (idx < NN) g_rowptr[idx] = thread_excl + pref[j];
    }
    if (tid == 1023) g_rowptr[NN] = thread_excl + s;  // == NE
}

// Atomic-free scatter: pos = rowptr[dst] + rank (rank captured during hist).
__global__ void k_scatter(const int* __restrict__ src, const int* __restrict__ dst) {
    int e = blockIdx.x * blockDim.x + threadIdx.x;
    if (e < NE) {
        int pos = g_rowptr[dst[e]] + g_rank[e];
        g_csr[pos] = src[e];
    }
}

// -------- layer 1 fused: aggregate x (F=10) + @W1 + b1 + relu + split ------
// Lane-packed gather: 10 lanes per edge, 3 edges per warp-iteration
// (g = lane/10 picks the edge, f = lane%10 the feature), 2-deep unroll.
// Partials folded into lanes 0-9 with two shfl_down steps.
__global__ void __launch_bounds__(512) k_layer1(const float* __restrict__ x,
                                                const float* __restrict__ W1,
                                                const float* __restrict__ b1) {
    __shared__ float Ws[F0 * F1];
    __shared__ float bs[F1];
    int t = threadIdx.x;
    for (int i = t; i < F0 * F1; i += 512) Ws[i] = W1[i];
    if (t < F1) bs[t] = b1[t];
    __syncthreads();

    int w = blockIdx.x * 16 + (t >> 5);
    int lane = t & 31;
    if (w >= NN) return;

    // lane -> (edge group g in 0..2, feature f in 0..9); lanes 30,31 idle
    int g = lane >= 30 ? 0 : (lane >= 20 ? 2 : (lane >= 10 ? 1 : 0));
    int f = lane - (g == 1 ? 10 : (g == 2 ? 20 : 0));
    bool active = lane < 30;

    float dn = g_dinv[w];
    float acc = 0.f;
    if (g == 0 && active) acc = dn * x[w * F0 + f];   // self loop (group 0 only)

    int b = g_rowptr[w], e = g_rowptr[w + 1];
    int i = b + g;
    // 2-deep unroll over this group's strided edge list (stride 3)
    for (; i + 3 < e; i += 6) {
        int s0 = 0, s1 = 0;
        if (active) { s0 = g_csr[i]; s1 = g_csr[i + 3]; }
        float c0 = 0.f, c1 = 0.f, x0 = 0.f, x1 = 0.f;
        if (active) {
            c0 = g_dinv[s0]; c1 = g_dinv[s1];
            x0 = x[s0 * F0 + f]; x1 = x[s1 * F0 + f];
        }
        acc += c0 * x0;
        acc += c1 * x1;
    }
    for (; i < e; i += 3) {
        if (active) {
            int s = g_csr[i];
            acc += g_dinv[s] * x[s * F0 + f];
        }
    }

    // fold 3 group partials into lanes 0..9
    float a1 = __shfl_down_sync(0xffffffffu, acc, 10);
    float a2 = __shfl_down_sync(0xffffffffu, acc, 20);
    acc = (acc + a1 + a2) * dn;               // valid in lanes 0..9

    // broadcast the 10 aggregate features to all lanes
    float a[F0];
    #pragma unroll
    for (int k = 0; k < F0; k++) a[k] = __shfl_sync(0xffffffffu, acc, k);

    #pragma unroll
    for (int j = 0; j < 8; j++) {
        int col = lane + j * 32;
        float o = bs[col];
        #pragma unroll
        for (int k = 0; k < F0; k++) o += a[k] * Ws[k * F1 + col];
        float v = fmaxf(o, 0.f);
        __nv_bfloat16 h = __float2bfloat16(v);
        __nv_bfloat16 l = __float2bfloat16(v - __bfloat162float(h));
        g_h1hi[w * F1 + col] = h;
        g_h1lo[w * F1 + col] = l;
    }
}

// ---------------- layer 2 GEMM (tensor cores, split-bf16) -------------------
// D[NP2,128] = h1[NP2,256] @ W2[256,128], 3-pass split bf16:
//   acc += a_hi*b_hi + a_lo*b_hi + a_hi*b_lo     (lo*lo dropped, ~2^-16)
__device__ __forceinline__ void mma_bf16(float* d, const unsigned* a,
                                         unsigned b0, unsigned b1) {
    asm volatile(
        "mma.sync.aligned.m16n8k16.row.col.f32.bf16.bf16.f32 "
        "{%0,%1,%2,%3}, {%4,%5,%6,%7}, {%8,%9}, {%0,%1,%2,%3};\n"
        : "+f"(d[0]), "+f"(d[1]), "+f"(d[2]), "+f"(d[3])
        : "r"(a[0]), "r"(a[1]), "r"(a[2]), "r"(a[3]), "r"(b0), "r"(b1));
}

#define KP 72   // smem B row stride (elems): conflict-free, 16B-aligned

__global__ void __launch_bounds__(256, 2) k_gemm2() {
    __shared__ __nv_bfloat16 bhi[F2 * KP];   // [n][k-chunk]
    __shared__ __nv_bfloat16 blo[F2 * KP];
    int t = threadIdx.x;
    int w = t >> 5, lane = t & 31;
    int r0 = blockIdx.x * 128;
    int mrow = r0 + w * 16 + (lane >> 2);    // A/D fragment top row
    int kq = (lane & 3) * 2;                 // k offset within 8

    float acc[16][4];
    #pragma unroll
    for (int i = 0; i < 16; i++)
        #pragma unroll
        for (int j = 0; j < 4; j++) acc[i][j] = 0.f;

    for (int kc = 0; kc < F1; kc += 64) {
        #pragma unroll
        for (int i = 0; i < 4; i++) {
            int idx = t + i * 256;           // 0..1023
            int n = idx >> 3, seg = idx & 7; // 8 x uint4 per row
            *(uint4*)&bhi[n * KP + seg * 8] =
                *(const uint4*)&g_w2thi[n * F1 + kc + seg * 8];
            *(uint4*)&blo[n * KP + seg * 8] =
                *(const uint4*)&g_w2tlo[n * F1 + kc + seg * 8];
        }
        __syncthreads();

        #pragma unroll
        for (int ks = 0; ks < 4; ks++) {
            int kg = kc + ks * 16 + kq;      // global k for A
            unsigned ahi[4], alo[4];
            ahi[0] = *(const unsigned*)&g_h1hi[ mrow      * F1 + kg];
            ahi[1] = *(const unsigned*)&g_h1hi[(mrow + 8) * F1 + kg];
            ahi[2] = *(const unsigned*)&g_h1hi[ mrow      * F1 + kg + 8];
            ahi[3] = *(const unsigned*)&g_h1hi[(mrow + 8) * F1 + kg + 8];
            alo[0] = *(const unsigned*)&g_h1lo[ mrow      * F1 + kg];
            alo[1] = *(const unsigned*)&g_h1lo[(mrow + 8) * F1 + kg];
            alo[2] = *(const unsigned*)&g_h1lo[ mrow      * F1 + kg + 8];
            alo[3] = *(const unsigned*)&g_h1lo[(mrow + 8) * F1 + kg + 8];
            int kl = ks * 16 + kq;           // chunk-local k for B
            #pragma unroll
            for (int nt = 0; nt < 16; nt++) {
                int nrow = nt * 8 + (lane >> 2);
                unsigned bh0 = *(const unsigned*)&bhi[nrow * KP + kl];
                unsigned bh1 = *(const unsigned*)&bhi[nrow * KP + kl + 8];
                unsigned bl0 = *(const unsigned*)&blo[nrow * KP + kl];
                unsigned bl1 = *(const unsigned*)&blo[nrow * KP + kl + 8];
                mma_bf16(acc[nt], ahi, bh0, bh1);
                mma_bf16(acc[nt], alo, bh0, bh1);
                mma_bf16(acc[nt], ahi, bl0, bl1);
            }
        }
        __syncthreads();
    }

    #pragma unroll
    for (int nt = 0; nt < 16; nt++) {
        int col = nt * 8 + (lane & 3) * 2;
        *(float2*)&g_t2[ mrow      * F2 + col] = make_float2(acc[nt][0], acc[nt][1]);
        *(float2*)&g_t2[(mrow + 8) * F2 + col] = make_float2(acc[nt][2], acc[nt][3]);
    }
}

// ------- layer 2 aggregation + bias + relu + layer-3 dot (fused) -----------
// 4-way unrolled gather: 4 independent csr->dinv->t2 chains in flight.
__global__ void k_agg2dot(const float* __restrict__ b2, const float* __restrict__ W3) {
    int w = (blockIdx.x * blockDim.x + threadIdx.x) >> 5;
    int lane = threadIdx.x & 31;
    if (w >= NN) return;
    float dn = g_dinv[w];
    int c4 = lane * 4;
    float4 sv = *(const float4*)&g_t2[w * F2 + c4];
    float4 acc = make_float4(dn * sv.x, dn * sv.y, dn * sv.z, dn * sv.w);
    int b = g_rowptr[w], e = g_rowptr[w + 1];
    int i = b;
    for (; i + 4 <= e; i += 4) {
        int s0 = g_csr[i + 0];
        int s1 = g_csr[i + 1];
        int s2 = g_csr[i + 2];
        int s3 = g_csr[i + 3];
        float c0 = g_dinv[s0];
        float c1 = g_dinv[s1];
        float c2 = g_dinv[s2];
        float c3 = g_dinv[s3];
        float4 v0 = *(const float4*)&g_t2[s0 * F2 + c4];
        float4 v1 = *(const float4*)&g_t2[s1 * F2 + c4];
        float4 v2 = *(const float4*)&g_t2[s2 * F2 + c4];
        float4 v3v = *(const float4*)&g_t2[s3 * F2 + c4];
        acc.x += c0 * v0.x; acc.y += c0 * v0.y; acc.z += c0 * v0.z; acc.w += c0 * v0.w;
        acc.x += c1 * v1.x; acc.y += c1 * v1.y; acc.z += c1 * v1.z; acc.w += c1 * v1.w;
        acc.x += c2 * v2.x; acc.y += c2 * v2.y; acc.z += c2 * v2.z; acc.w += c2 * v2.w;
        acc.x += c3 * v3v.x; acc.y += c3 * v3v.y; acc.z += c3 * v3v.z; acc.w += c3 * v3v.w;
    }
    for (; i < e; i++) {
        int s = g_csr[i];
        float c = g_dinv[s];
        float4 v = *(const float4*)&g_t2[s * F2 + c4];
        acc.x += c * v.x; acc.y += c * v.y; acc.z += c * v.z; acc.w += c * v.w;
    }
    float4 bb = *(const float4*)&b2[c4];
    float4 h;
    h.x = fmaxf(dn * acc.x + bb.x, 0.f);
    h.y = fmaxf(dn * acc.y + bb.y, 0.f);
    h.z = fmaxf(dn * acc.z + bb.z, 0.f);
    h.w = fmaxf(dn * acc.w + bb.w, 0.f);
    float4 v3 = *(const float4*)&W3[c4];
    float s = h.x * v3.x + h.y * v3.y + h.z * v3.z + h.w * v3.w;
    #pragma unroll
    for (int o = 16; o > 0; o >>= 1) s += __shfl_down_sync(0xffffffffu, s, o);
    if (lane == 0) g_t3[w] = s;
}

// ---------------- final aggregation over t3 (4-way unrolled) ----------------
__global__ void k_agg3(const float* __restrict__ b3, float* __restrict__ out) {
    int n = blockIdx.x * blockDim.x + threadIdx.x;
    if (n >= NN) return;
    float dn = g_dinv[n];
    float acc = dn * g_t3[n];
    int b = g_rowptr[n], e = g_rowptr[n + 1];
    int i = b;
    for (; i + 4 <= e; i += 4) {
        int s0 = g_csr[i + 0];
        int s1 = g_csr[i + 1];
        int s2 = g_csr[i + 2];
        int s3 = g_csr[i + 3];
        acc += g_dinv[s0] * g_t3[s0];
        acc += g_dinv[s1] * g_t3[s1];
        acc += g_dinv[s2] * g_t3[s2];
        acc += g_dinv[s3] * g_t3[s3];
    }
    for (; i < e; i++) {
        int s = g_csr[i];
        acc += g_dinv[s] * g_t3[s];
    }
    out[n] = dn * acc + b3[0];
}

// ---------------- launch ----------------------------------------------------
extern "C" void kernel_launch(void* const* d_in, const int* in_sizes, int n_in,
                              void* d_out, int out_size) {
    const float* x   = (const float*)d_in[0];
    const int*   ei  = (const int*)d_in[1];
    const float* W1  = (const float*)d_in[2];
    const float* b1  = (const float*)d_in[3];
    const float* W2  = (const float*)d_in[4];
    const float* b2  = (const float*)d_in[5];
    const float* W3  = (const float*)d_in[6];
    const float* b3  = (const float*)d_in[7];
    float* out = (float*)d_out;
    const int* src = ei;
    const int* dst = ei + NE;

    k_hist<<<HIST_BLKS + 128, 256>>>(dst, W2);     // hist + W2 split-bf16^T
    k_scan_fused<<<1, 1024>>>();                   // scan + dinv + cnt re-zero
    k_scatter<<<(NE + 255) / 256, 256>>>(src, dst);

    k_layer1<<<(NN + 15) / 16, 512>>>(x, W1, b1);  // aggx + gemm1 fused
    k_gemm2<<<NP2 / 128, 256>>>();
    k_agg2dot<<<(NN * 32 + 255) / 256, 256>>>(b2, W3);
    k_agg3<<<(NN + 255) / 256, 256>>>(b3, out);
}